// round 12
// baseline (speedup 1.0000x reference)
#include <cuda_runtime.h>
#include <cuda_bf16.h>
#include <cstdint>

#define BATCH 8
#define SEQ   2048
#define CDIM  768
#define KD    768
#define MQ    (BATCH*SEQ)

typedef __nv_bfloat16 bf16;

// ---------------- scratch (device globals; allocation-free rule) -------------
__device__ bf16  g_qx[(size_t)MQ*CDIM];              // qx bf16
__device__ bf16  g_kx[(size_t)MQ*CDIM];              // kx bf16
__device__ bf16  g_wt[(size_t)2*KD*CDIM];            // WqT, WkT bf16
__device__ bf16  g_mt[(size_t)KD*CDIM];              // MT[c'][c] = M[c][c']
__device__ bf16  g_qp[(size_t)MQ*KD];                // q' = qx @ M
__device__ bf16  g_e [(size_t)BATCH*SEQ*SEQ];        // E' = exp(S*scale)-1
__device__ bf16  g_vt[(size_t)BATCH*CDIM*SEQ];       // V^T bf16
__device__ float g_colsum[(size_t)BATCH*CDIM];       // colsum of V (fp32 exact)
__device__ float g_inv  [(size_t)MQ];                // 1/(SEQ + rowsum(E'))

// ---------------- helpers ----------------------------------------------------
__device__ __forceinline__ uint32_t smem_u32(const void* p) {
    uint32_t a;
    asm("{ .reg .u64 t; cvta.to.shared.u64 t, %1; cvt.u32.u64 %0, t; }" : "=r"(a) : "l"(p));
    return a;
}
__device__ __forceinline__ void cp16(uint32_t dst, const void* src) {
    asm volatile("cp.async.cg.shared.global [%0], [%1], 16;" :: "r"(dst), "l"(src));
}
__device__ __forceinline__ void cp_commit() {
    asm volatile("cp.async.commit_group;" ::: "memory");
}
template <int N>
__device__ __forceinline__ void cp_wait() {
    asm volatile("cp.async.wait_group %0;" :: "n"(N) : "memory");
}
__device__ __forceinline__ void ldsm4(uint32_t* r, uint32_t addr) {
    asm volatile("ldmatrix.sync.aligned.m8n8.x4.shared.b16 {%0,%1,%2,%3}, [%4];"
                 : "=r"(r[0]), "=r"(r[1]), "=r"(r[2]), "=r"(r[3]) : "r"(addr));
}
__device__ __forceinline__ void mma16816(float* c, const uint32_t* a, const uint32_t* b) {
    asm volatile(
        "mma.sync.aligned.m16n8k16.row.col.f32.bf16.bf16.f32 "
        "{%0,%1,%2,%3}, {%4,%5,%6,%7}, {%8,%9}, {%0,%1,%2,%3};"
        : "+f"(c[0]), "+f"(c[1]), "+f"(c[2]), "+f"(c[3])
        : "r"(a[0]), "r"(a[1]), "r"(a[2]), "r"(a[3]), "r"(b[0]), "r"(b[1]));
}

// ---------------- single-bf16 NT GEMM via mma.sync (R7 core, 2 CTAs/SM) ------
// C[m,n] = sum_k A[m,k]*B[n,k]; A,B bf16, K-major, fp32 accum.
// Block 128x128, K-chunk 32, 4-stage cp.async pipeline, 8 warps (64x32 each).
// MODE 0: C -> bf16 plain.
// MODE 3: C -> bf16 of (exp(c*scale)-1).
// MODE 4: C -> fp32 of (c + colsum[n]) * inv_denom[m].
#define BM 128
#define BN 128
#define BK 32
#define STAGES 4
#define PITCH_B 80               // bytes per smem row (32 bf16 + 8 pad)
#define MAT_B  (128*PITCH_B)     // 10240 bytes per matrix tile
#define STAGE_B (2*MAT_B)
#define GSMEM_BYTES (STAGES*STAGE_B)   // 81920 -> 2 CTAs = 160 KB/SM

template <int MODE>
__global__ void __launch_bounds__(256, 2) gemm_mma(
    const bf16* __restrict__ A, const bf16* __restrict__ B,
    float* __restrict__ Cf, bf16* __restrict__ Cb16,
    const float* __restrict__ bias, const float* __restrict__ denom, float scale,
    int K, int N, long long sA, long long sB, long long sC)
{
    extern __shared__ char smem[];
    const uint32_t smem0 = smem_u32(smem);

    const int tid = threadIdx.x;
    const int wid = tid >> 5;
    const int lane = tid & 31;
    const int m0 = blockIdx.y * BM;
    const int n0 = blockIdx.x * BN;
    const int warp_m = (wid & 1) * 64;
    const int warp_n = (wid >> 1) * 32;

    const bf16* pA = A + (size_t)blockIdx.z * sA;
    const bf16* pB = B + (size_t)blockIdx.z * sB;

    float acc[4][4][4];
#pragma unroll
    for (int a = 0; a < 4; a++)
#pragma unroll
        for (int b = 0; b < 4; b++)
#pragma unroll
            for (int c = 0; c < 4; c++) acc[a][b][c] = 0.0f;

    const int nch = K / BK;

    auto load_stage = [&](int buf, int k0) {
        const uint32_t sb = smem0 + (uint32_t)buf * STAGE_B;
#pragma unroll
        for (int p = 0; p < 2; p++) {
            const int task = tid + p * 256;
            const int row = task >> 2;
            const int seg = task & 3;
            const uint32_t off = (uint32_t)(row * PITCH_B + seg * 16);
            const int ge = k0 + seg * 8;
            cp16(sb +         off, pA + (size_t)(m0 + row) * K + ge);
            cp16(sb + MAT_B + off, pB + (size_t)(n0 + row) * K + ge);
        }
    };

#pragma unroll
    for (int s = 0; s < STAGES - 1; s++) {
        if (s < nch) load_stage(s, s * BK);
        cp_commit();
    }

    const uint32_t a_off = (uint32_t)((lane & 15) * PITCH_B + ((lane >> 4) << 3) * 2);
    const uint32_t b_off = (uint32_t)(((((lane >> 4) << 3) + (lane & 7)) * PITCH_B)
                                      + (((lane >> 3) & 1) << 3) * 2);

    for (int ch = 0; ch < nch; ch++) {
        cp_wait<STAGES - 2>();
        __syncthreads();

        const int nxt = ch + STAGES - 1;
        if (nxt < nch) load_stage(nxt % STAGES, nxt * BK);
        cp_commit();

        const uint32_t sb = smem0 + (uint32_t)(ch % STAGES) * STAGE_B;
        const uint32_t sA_ = sb, sB_ = sb + MAT_B;

#pragma unroll
        for (int ks = 0; ks < 2; ks++) {
            const uint32_t kb = (uint32_t)(ks * 16 * 2);
            uint32_t ar[4][4];
#pragma unroll
            for (int mi = 0; mi < 4; mi++)
                ldsm4(ar[mi], sA_ + (uint32_t)((warp_m + mi * 16) * PITCH_B) + a_off + kb);
            uint32_t br[2][4];
#pragma unroll
            for (int nj = 0; nj < 2; nj++)
                ldsm4(br[nj], sB_ + (uint32_t)((warp_n + nj * 16) * PITCH_B) + b_off + kb);
#pragma unroll
            for (int mi = 0; mi < 4; mi++)
#pragma unroll
                for (int ni = 0; ni < 4; ni++)
                    mma16816(acc[mi][ni], ar[mi], &br[ni >> 1][(ni & 1) * 2]);
        }
    }
    cp_wait<0>();

    // -------- epilogue ------------------------------------------------------
#pragma unroll
    for (int mi = 0; mi < 4; mi++) {
#pragma unroll
        for (int ni = 0; ni < 4; ni++) {
            const int m = m0 + warp_m + mi * 16 + (lane >> 2);
            const int n = n0 + warp_n + ni * 8 + (lane & 3) * 2;
            float c0 = acc[mi][ni][0], c1 = acc[mi][ni][1];
            float c2 = acc[mi][ni][2], c3 = acc[mi][ni][3];
            if (MODE == 0 || MODE == 3) {
                if (MODE == 3) {
                    c0 = __expf(c0 * scale) - 1.0f;
                    c1 = __expf(c1 * scale) - 1.0f;
                    c2 = __expf(c2 * scale) - 1.0f;
                    c3 = __expf(c3 * scale) - 1.0f;
                }
                bf16* Cz = Cb16 + (size_t)blockIdx.z * sC;
                __nv_bfloat162 h0 = __floats2bfloat162_rn(c0, c1);
                __nv_bfloat162 h1 = __floats2bfloat162_rn(c2, c3);
                *(uint32_t*)(Cz + (size_t)m * N + n)       = reinterpret_cast<uint32_t&>(h0);
                *(uint32_t*)(Cz + (size_t)(m + 8) * N + n) = reinterpret_cast<uint32_t&>(h1);
            } else {  // MODE 4
                float* Cb = Cf + (size_t)blockIdx.z * sC;
                float2 bv = *(const float2*)(bias + (size_t)blockIdx.z * CDIM + n);
                float i0 = denom[(size_t)blockIdx.z * SEQ + m];
                float i1 = denom[(size_t)blockIdx.z * SEQ + m + 8];
                *(float2*)(Cb + (size_t)m * N + n) =
                    make_float2((c0 + bv.x) * i0, (c1 + bv.y) * i0);
                *(float2*)(Cb + (size_t)(m + 8) * N + n) =
                    make_float2((c2 + bv.x) * i1, (c3 + bv.y) * i1);
            }
        }
    }
}

// ---------------- elementwise fp32 -> bf16 -----------------------------------
__global__ void __launch_bounds__(256) convert_hi(
    const float* __restrict__ x, bf16* __restrict__ h, size_t n)
{
    size_t i = ((size_t)blockIdx.x * 256 + threadIdx.x) * 8;
    if (i >= n) return;
    float4 a = *(const float4*)(x + i);
    float4 b = *(const float4*)(x + i + 4);
    __nv_bfloat162 h0 = __floats2bfloat162_rn(a.x, a.y);
    __nv_bfloat162 h1 = __floats2bfloat162_rn(a.z, a.w);
    __nv_bfloat162 h2 = __floats2bfloat162_rn(b.x, b.y);
    __nv_bfloat162 h3 = __floats2bfloat162_rn(b.z, b.w);
    *(uint4*)(h + i) = make_uint4(
        reinterpret_cast<uint32_t&>(h0), reinterpret_cast<uint32_t&>(h1),
        reinterpret_cast<uint32_t&>(h2), reinterpret_cast<uint32_t&>(h3));
}

// ---------------- generic transpose: [R,C] fp32 -> [C,R] bf16 ----------------
__global__ void __launch_bounds__(256) transpose_convert(
    const float* __restrict__ in, bf16* __restrict__ out,
    int R, int C, long long sIn, long long sOut)
{
    __shared__ float t[32][33];
    const float* ib = in + (size_t)blockIdx.z * sIn;
    bf16* ob = out + (size_t)blockIdx.z * sOut;
    const int c0 = blockIdx.x * 32, r0 = blockIdx.y * 32;
    for (int r = threadIdx.y; r < 32; r += 8)
        t[r][threadIdx.x] = ib[(size_t)(r0 + r) * C + c0 + threadIdx.x];
    __syncthreads();
    for (int r = threadIdx.y; r < 32; r += 8)
        ob[(size_t)(c0 + r) * R + r0 + threadIdx.x] = __float2bfloat16(t[threadIdx.x][r]);
}

// ---------------- column sum of V: colsum[b][c] = sum_n v[b][n][c] ----------
__global__ void __launch_bounds__(256) colsum_v(
    const float* __restrict__ v, float* __restrict__ cs)
{
    const int b = blockIdx.y;
    const int c = blockIdx.x * 256 + threadIdx.x;
    const float* vb = v + (size_t)b * SEQ * CDIM + c;
    float s0 = 0.f, s1 = 0.f, s2 = 0.f, s3 = 0.f;
#pragma unroll 4
    for (int i = 0; i < SEQ; i += 4) {
        s0 += vb[(size_t)(i + 0) * CDIM];
        s1 += vb[(size_t)(i + 1) * CDIM];
        s2 += vb[(size_t)(i + 2) * CDIM];
        s3 += vb[(size_t)(i + 3) * CDIM];
    }
    cs[(size_t)b * CDIM + c] = s0 + s1 + s2 + s3;
}

// ---------------- row sum of E' -> inv_denom = 1/(SEQ + rowsum) -------------
__global__ void __launch_bounds__(256) rowsum_exp(
    const bf16* __restrict__ E, float* __restrict__ inv)
{
    const bf16* row = E + (size_t)blockIdx.x * SEQ;
    const int tid = threadIdx.x;
    uint4 v = *(const uint4*)(row + tid * 8);
    const __nv_bfloat162* p = reinterpret_cast<const __nv_bfloat162*>(&v);
    float s = 0.f;
#pragma unroll
    for (int j = 0; j < 4; j++) {
        float2 f = __bfloat1622float2(p[j]);
        s += f.x + f.y;
    }
    __shared__ float red[256];
    red[tid] = s; __syncthreads();
    for (int st = 128; st > 0; st >>= 1) {
        if (tid < st) red[tid] += red[tid + st];
        __syncthreads();
    }
    if (tid == 0) inv[blockIdx.x] = 1.0f / ((float)SEQ + red[0]);
}

// ---------------- launch -----------------------------------------------------
extern "C" void kernel_launch(void* const* d_in, const int* in_sizes, int n_in,
                              void* d_out, int out_size)
{
    const float* q_x = (const float*)d_in[0];
    const float* k_x = (const float*)d_in[1];
    const float* v_x = (const float*)d_in[2];
    const float* Wq  = (const float*)d_in[3];
    const float* Wk  = (const float*)d_in[4];
    float* out = (float*)d_out;

    bf16 *qx, *kx, *wt, *mt, *qp, *e, *vt;
    float *colsum, *inv;
    cudaGetSymbolAddress((void**)&qx, g_qx);
    cudaGetSymbolAddress((void**)&kx, g_kx);
    cudaGetSymbolAddress((void**)&wt, g_wt);
    cudaGetSymbolAddress((void**)&mt, g_mt);
    cudaGetSymbolAddress((void**)&qp, g_qp);
    cudaGetSymbolAddress((void**)&e,  g_e);
    cudaGetSymbolAddress((void**)&vt, g_vt);
    cudaGetSymbolAddress((void**)&colsum, g_colsum);
    cudaGetSymbolAddress((void**)&inv, g_inv);

    cudaFuncSetAttribute(gemm_mma<0>, cudaFuncAttributeMaxDynamicSharedMemorySize, GSMEM_BYTES);
    cudaFuncSetAttribute(gemm_mma<3>, cudaFuncAttributeMaxDynamicSharedMemorySize, GSMEM_BYTES);
    cudaFuncSetAttribute(gemm_mma<4>, cudaFuncAttributeMaxDynamicSharedMemorySize, GSMEM_BYTES);

    const size_t nx = (size_t)MQ * CDIM;
    const size_t nw = (size_t)KD * CDIM;

    // 1) converts / transposes / V colsum
    convert_hi<<<(unsigned)(nx / 8 / 256), 256>>>(q_x, qx, nx);
    convert_hi<<<(unsigned)(nx / 8 / 256), 256>>>(k_x, kx, nx);
    transpose_convert<<<dim3(CDIM / 32, KD / 32, 1), dim3(32, 8)>>>(
        Wq, wt, KD, CDIM, 0, 0);                         // WqT [c][d]
    transpose_convert<<<dim3(CDIM / 32, KD / 32, 1), dim3(32, 8)>>>(
        Wk, wt + nw, KD, CDIM, 0, 0);                    // WkT [c'][d]
    transpose_convert<<<dim3(CDIM / 32, SEQ / 32, BATCH), dim3(32, 8)>>>(
        v_x, vt, SEQ, CDIM, (long long)SEQ * CDIM, (long long)CDIM * SEQ);
    colsum_v<<<dim3(CDIM / 256, BATCH), 256>>>(v_x, colsum);

    // 2) MT[c'][c] = sum_d WkT[c'][d] * WqT[c][d]  (= M[c][c'])
    gemm_mma<0><<<dim3(CDIM / BN, KD / BM, 1), 256, GSMEM_BYTES>>>(
        wt + nw, wt, nullptr, mt, nullptr, nullptr, 0.f, KD, CDIM, 0, 0, 0);

    // 3) q'[m][c'] = sum_c qx[m][c] * MT[c'][c]
    gemm_mma<0><<<dim3(KD / BN, MQ / BM, 1), 256, GSMEM_BYTES>>>(
        qx, mt, nullptr, qp, nullptr, nullptr, 0.f, CDIM, KD, 0, 0, 0);

    // 4) E' = exp((q' @ kx^T) * scale) - 1  per batch (bf16)
    gemm_mma<3><<<dim3(SEQ / BN, SEQ / BM, BATCH), 256, GSMEM_BYTES>>>(
        qp, kx, nullptr, e, nullptr, nullptr, 1.0f / (float)KD, KD, SEQ,
        (long long)SEQ * KD, (long long)SEQ * CDIM, (long long)SEQ * SEQ);

    // 5) inv_denom[m] = 1 / (SEQ + rowsum(E'))
    rowsum_exp<<<MQ, 256>>>(e, inv);

    // 6) out = (E' @ Vt^T + colsum) * inv_denom  per batch (fp32)
    gemm_mma<4><<<dim3(CDIM / BN, SEQ / BM, BATCH), 256, GSMEM_BYTES>>>(
        e, vt, out, nullptr, colsum, inv, 0.f, SEQ, CDIM,
        (long long)SEQ * SEQ, (long long)CDIM * SEQ, (long long)SEQ * CDIM);
}

// round 14
// speedup vs baseline: 1.0568x; 1.0568x over previous
#include <cuda_runtime.h>
#include <cuda_bf16.h>
#include <cstdint>

#define BATCH 8
#define SEQ   2048
#define CDIM  768
#define KD    768
#define MQ    (BATCH*SEQ)

typedef __nv_bfloat16 bf16;

// ---------------- scratch (device globals; allocation-free rule) -------------
__device__ bf16  g_qx[(size_t)MQ*CDIM];              // qx bf16
__device__ bf16  g_kx[(size_t)MQ*CDIM];              // kx bf16
__device__ bf16  g_wt[(size_t)2*KD*CDIM];            // WqT, WkT bf16
__device__ bf16  g_mt[(size_t)KD*CDIM];              // MT[c'][c] = M[c][c']
__device__ bf16  g_qp[(size_t)MQ*KD];                // q' = qx @ M
__device__ bf16  g_e [(size_t)BATCH*SEQ*SEQ];        // E' = exp(S*scale)-1
__device__ bf16  g_vt[(size_t)BATCH*CDIM*SEQ];       // V^T bf16
__device__ float g_colsum[(size_t)BATCH*CDIM];       // colsum of V (fp32 exact)
__device__ float g_inv  [(size_t)MQ];                // 1/(SEQ + rowsum(E'))

// ---------------- helpers ----------------------------------------------------
__device__ __forceinline__ uint32_t smem_u32(const void* p) {
    uint32_t a;
    asm("{ .reg .u64 t; cvta.to.shared.u64 t, %1; cvt.u32.u64 %0, t; }" : "=r"(a) : "l"(p));
    return a;
}
__device__ __forceinline__ void cp16(uint32_t dst, const void* src) {
    asm volatile("cp.async.cg.shared.global [%0], [%1], 16;" :: "r"(dst), "l"(src));
}
__device__ __forceinline__ void cp_commit() {
    asm volatile("cp.async.commit_group;" ::: "memory");
}
template <int N>
__device__ __forceinline__ void cp_wait() {
    asm volatile("cp.async.wait_group %0;" :: "n"(N) : "memory");
}
__device__ __forceinline__ void ldsm4(uint32_t* r, uint32_t addr) {
    asm volatile("ldmatrix.sync.aligned.m8n8.x4.shared.b16 {%0,%1,%2,%3}, [%4];"
                 : "=r"(r[0]), "=r"(r[1]), "=r"(r[2]), "=r"(r[3]) : "r"(addr));
}
__device__ __forceinline__ void mma16816(float* c, const uint32_t* a, const uint32_t* b) {
    asm volatile(
        "mma.sync.aligned.m16n8k16.row.col.f32.bf16.bf16.f32 "
        "{%0,%1,%2,%3}, {%4,%5,%6,%7}, {%8,%9}, {%0,%1,%2,%3};"
        : "+f"(c[0]), "+f"(c[1]), "+f"(c[2]), "+f"(c[3])
        : "r"(a[0]), "r"(a[1]), "r"(a[2]), "r"(a[3]), "r"(b[0]), "r"(b[1]));
}

// ---------------- single-bf16 NT GEMM via mma.sync ---------------------------
// C[m,n] = sum_k A[m,k]*B[n,k]; A,B bf16, K-major, fp32 accum.
// Block 128x128, K-chunk 64, 3-stage cp.async pipeline, 8 warps (64x32 each),
// register-level fragment double-buffering (ldsm for step s+1 before MMAs of s).
// MODE 0: C -> bf16 plain.
// MODE 3: C -> bf16 of (exp(c*scale)-1).
// MODE 4: C -> fp32 of (c + colsum[n]) * inv_denom[m].
#define BM 128
#define BN 128
#define BK 64
#define KSTEPS (BK/16)           // 4
#define STAGES 3
#define PITCH_B 144              // bytes per smem row (64 bf16 + 16 pad)
#define MAT_B  (128*PITCH_B)     // 18432 bytes per matrix tile
#define STAGE_B (2*MAT_B)        // 36864
#define GSMEM_BYTES (STAGES*STAGE_B)   // 110592

template <int MODE>
__global__ void __launch_bounds__(256) gemm_mma(
    const bf16* __restrict__ A, const bf16* __restrict__ B,
    float* __restrict__ Cf, bf16* __restrict__ Cb16,
    const float* __restrict__ bias, const float* __restrict__ denom, float scale,
    int K, int N, long long sA, long long sB, long long sC)
{
    extern __shared__ char smem[];
    const uint32_t smem0 = smem_u32(smem);

    const int tid = threadIdx.x;
    const int wid = tid >> 5;
    const int lane = tid & 31;
    const int m0 = blockIdx.y * BM;
    const int n0 = blockIdx.x * BN;
    const int warp_m = (wid & 1) * 64;
    const int warp_n = (wid >> 1) * 32;

    const bf16* pA = A + (size_t)blockIdx.z * sA;
    const bf16* pB = B + (size_t)blockIdx.z * sB;

    float acc[4][4][4];
#pragma unroll
    for (int a = 0; a < 4; a++)
#pragma unroll
        for (int b = 0; b < 4; b++)
#pragma unroll
            for (int c = 0; c < 4; c++) acc[a][b][c] = 0.0f;

    const int nch = K / BK;

    // stage loader: A 128 rows + B 128 rows, 128B each = 8 cp16/thread
    auto load_stage = [&](int buf, int k0) {
        const uint32_t sb = smem0 + (uint32_t)buf * STAGE_B;
#pragma unroll
        for (int p = 0; p < 4; p++) {
            const int task = tid + p * 256;
            const int row = task >> 3;            // 8 segs per row
            const int seg = task & 7;
            const uint32_t off = (uint32_t)(row * PITCH_B + seg * 16);
            const int ge = k0 + seg * 8;
            cp16(sb +         off, pA + (size_t)(m0 + row) * K + ge);
            cp16(sb + MAT_B + off, pB + (size_t)(n0 + row) * K + ge);
        }
    };

#pragma unroll
    for (int s = 0; s < STAGES - 1; s++) {
        if (s < nch) load_stage(s, s * BK);
        cp_commit();
    }

    const uint32_t a_off = (uint32_t)((lane & 15) * PITCH_B + ((lane >> 4) << 3) * 2);
    const uint32_t b_off = (uint32_t)(((((lane >> 4) << 3) + (lane & 7)) * PITCH_B)
                                      + (((lane >> 3) & 1) << 3) * 2);

    uint32_t ar[2][4][4];       // fragment double buffers
    uint32_t br[2][2][4];

    for (int ch = 0; ch < nch; ch++) {
        cp_wait<STAGES - 2>();
        __syncthreads();

        const int nxt = ch + STAGES - 1;
        if (nxt < nch) load_stage(nxt % STAGES, nxt * BK);
        cp_commit();

        const uint32_t sb = smem0 + (uint32_t)(ch % STAGES) * STAGE_B;
        const uint32_t sA_ = sb, sB_ = sb + MAT_B;

        auto load_frags = [&](int ks, int pb) {
            const uint32_t kb = (uint32_t)(ks * 32);
#pragma unroll
            for (int mi = 0; mi < 4; mi++)
                ldsm4(ar[pb][mi], sA_ + (uint32_t)((warp_m + mi * 16) * PITCH_B) + a_off + kb);
#pragma unroll
            for (int nj = 0; nj < 2; nj++)
                ldsm4(br[pb][nj], sB_ + (uint32_t)((warp_n + nj * 16) * PITCH_B) + b_off + kb);
        };

        load_frags(0, 0);
#pragma unroll
        for (int ks = 0; ks < KSTEPS; ks++) {
            const int cur = ks & 1;
            if (ks + 1 < KSTEPS) load_frags(ks + 1, cur ^ 1);
#pragma unroll
            for (int mi = 0; mi < 4; mi++)
#pragma unroll
                for (int ni = 0; ni < 4; ni++)
                    mma16816(acc[mi][ni], ar[cur][mi], &br[cur][ni >> 1][(ni & 1) * 2]);
        }
    }
    cp_wait<0>();

    // -------- epilogue ------------------------------------------------------
#pragma unroll
    for (int mi = 0; mi < 4; mi++) {
#pragma unroll
        for (int ni = 0; ni < 4; ni++) {
            const int m = m0 + warp_m + mi * 16 + (lane >> 2);
            const int n = n0 + warp_n + ni * 8 + (lane & 3) * 2;
            float c0 = acc[mi][ni][0], c1 = acc[mi][ni][1];
            float c2 = acc[mi][ni][2], c3 = acc[mi][ni][3];
            if (MODE == 0 || MODE == 3) {
                if (MODE == 3) {
                    c0 = __expf(c0 * scale) - 1.0f;
                    c1 = __expf(c1 * scale) - 1.0f;
                    c2 = __expf(c2 * scale) - 1.0f;
                    c3 = __expf(c3 * scale) - 1.0f;
                }
                bf16* Cz = Cb16 + (size_t)blockIdx.z * sC;
                __nv_bfloat162 h0 = __floats2bfloat162_rn(c0, c1);
                __nv_bfloat162 h1 = __floats2bfloat162_rn(c2, c3);
                *(uint32_t*)(Cz + (size_t)m * N + n)       = reinterpret_cast<uint32_t&>(h0);
                *(uint32_t*)(Cz + (size_t)(m + 8) * N + n) = reinterpret_cast<uint32_t&>(h1);
            } else {  // MODE 4
                float* Cb = Cf + (size_t)blockIdx.z * sC;
                float2 bv = *(const float2*)(bias + (size_t)blockIdx.z * CDIM + n);
                float i0 = denom[(size_t)blockIdx.z * SEQ + m];
                float i1 = denom[(size_t)blockIdx.z * SEQ + m + 8];
                *(float2*)(Cb + (size_t)m * N + n) =
                    make_float2((c0 + bv.x) * i0, (c1 + bv.y) * i0);
                *(float2*)(Cb + (size_t)(m + 8) * N + n) =
                    make_float2((c2 + bv.x) * i1, (c3 + bv.y) * i1);
            }
        }
    }
}

// ---------------- elementwise fp32 -> bf16 -----------------------------------
__global__ void __launch_bounds__(256) convert_hi(
    const float* __restrict__ x, bf16* __restrict__ h, size_t n)
{
    size_t i = ((size_t)blockIdx.x * 256 + threadIdx.x) * 8;
    if (i >= n) return;
    float4 a = *(const float4*)(x + i);
    float4 b = *(const float4*)(x + i + 4);
    __nv_bfloat162 h0 = __floats2bfloat162_rn(a.x, a.y);
    __nv_bfloat162 h1 = __floats2bfloat162_rn(a.z, a.w);
    __nv_bfloat162 h2 = __floats2bfloat162_rn(b.x, b.y);
    __nv_bfloat162 h3 = __floats2bfloat162_rn(b.z, b.w);
    *(uint4*)(h + i) = make_uint4(
        reinterpret_cast<uint32_t&>(h0), reinterpret_cast<uint32_t&>(h1),
        reinterpret_cast<uint32_t&>(h2), reinterpret_cast<uint32_t&>(h3));
}

// ---------------- generic transpose: [R,C] fp32 -> [C,R] bf16 ----------------
__global__ void __launch_bounds__(256) transpose_convert(
    const float* __restrict__ in, bf16* __restrict__ out,
    int R, int C, long long sIn, long long sOut)
{
    __shared__ float t[32][33];
    const float* ib = in + (size_t)blockIdx.z * sIn;
    bf16* ob = out + (size_t)blockIdx.z * sOut;
    const int c0 = blockIdx.x * 32, r0 = blockIdx.y * 32;
    for (int r = threadIdx.y; r < 32; r += 8)
        t[r][threadIdx.x] = ib[(size_t)(r0 + r) * C + c0 + threadIdx.x];
    __syncthreads();
    for (int r = threadIdx.y; r < 32; r += 8)
        ob[(size_t)(c0 + r) * R + r0 + threadIdx.x] = __float2bfloat16(t[threadIdx.x][r]);
}

// ---------------- column sum of V: colsum[b][c] = sum_n v[b][n][c] ----------
__global__ void __launch_bounds__(256) colsum_v(
    const float* __restrict__ v, float* __restrict__ cs)
{
    const int b = blockIdx.y;
    const int c = blockIdx.x * 256 + threadIdx.x;
    const float* vb = v + (size_t)b * SEQ * CDIM + c;
    float s0 = 0.f, s1 = 0.f, s2 = 0.f, s3 = 0.f;
#pragma unroll 4
    for (int i = 0; i < SEQ; i += 4) {
        s0 += vb[(size_t)(i + 0) * CDIM];
        s1 += vb[(size_t)(i + 1) * CDIM];
        s2 += vb[(size_t)(i + 2) * CDIM];
        s3 += vb[(size_t)(i + 3) * CDIM];
    }
    cs[(size_t)b * CDIM + c] = s0 + s1 + s2 + s3;
}

// ---------------- row sum of E' -> inv_denom = 1/(SEQ + rowsum) -------------
__global__ void __launch_bounds__(256) rowsum_exp(
    const bf16* __restrict__ E, float* __restrict__ inv)
{
    const bf16* row = E + (size_t)blockIdx.x * SEQ;
    const int tid = threadIdx.x;
    uint4 v = *(const uint4*)(row + tid * 8);
    const __nv_bfloat162* p = reinterpret_cast<const __nv_bfloat162*>(&v);
    float s = 0.f;
#pragma unroll
    for (int j = 0; j < 4; j++) {
        float2 f = __bfloat1622float2(p[j]);
        s += f.x + f.y;
    }
    __shared__ float red[256];
    red[tid] = s; __syncthreads();
    for (int st = 128; st > 0; st >>= 1) {
        if (tid < st) red[tid] += red[tid + st];
        __syncthreads();
    }
    if (tid == 0) inv[blockIdx.x] = 1.0f / ((float)SEQ + red[0]);
}

// ---------------- launch -----------------------------------------------------
extern "C" void kernel_launch(void* const* d_in, const int* in_sizes, int n_in,
                              void* d_out, int out_size)
{
    const float* q_x = (const float*)d_in[0];
    const float* k_x = (const float*)d_in[1];
    const float* v_x = (const float*)d_in[2];
    const float* Wq  = (const float*)d_in[3];
    const float* Wk  = (const float*)d_in[4];
    float* out = (float*)d_out;

    bf16 *qx, *kx, *wt, *mt, *qp, *e, *vt;
    float *colsum, *inv;
    cudaGetSymbolAddress((void**)&qx, g_qx);
    cudaGetSymbolAddress((void**)&kx, g_kx);
    cudaGetSymbolAddress((void**)&wt, g_wt);
    cudaGetSymbolAddress((void**)&mt, g_mt);
    cudaGetSymbolAddress((void**)&qp, g_qp);
    cudaGetSymbolAddress((void**)&e,  g_e);
    cudaGetSymbolAddress((void**)&vt, g_vt);
    cudaGetSymbolAddress((void**)&colsum, g_colsum);
    cudaGetSymbolAddress((void**)&inv, g_inv);

    cudaFuncSetAttribute(gemm_mma<0>, cudaFuncAttributeMaxDynamicSharedMemorySize, GSMEM_BYTES);
    cudaFuncSetAttribute(gemm_mma<3>, cudaFuncAttributeMaxDynamicSharedMemorySize, GSMEM_BYTES);
    cudaFuncSetAttribute(gemm_mma<4>, cudaFuncAttributeMaxDynamicSharedMemorySize, GSMEM_BYTES);

    const size_t nx = (size_t)MQ * CDIM;
    const size_t nw = (size_t)KD * CDIM;

    // 1) converts / transposes / V colsum
    convert_hi<<<(unsigned)(nx / 8 / 256), 256>>>(q_x, qx, nx);
    convert_hi<<<(unsigned)(nx / 8 / 256), 256>>>(k_x, kx, nx);
    transpose_convert<<<dim3(CDIM / 32, KD / 32, 1), dim3(32, 8)>>>(
        Wq, wt, KD, CDIM, 0, 0);                         // WqT [c][d]
    transpose_convert<<<dim3(CDIM / 32, KD / 32, 1), dim3(32, 8)>>>(
        Wk, wt + nw, KD, CDIM, 0, 0);                    // WkT [c'][d]
    transpose_convert<<<dim3(CDIM / 32, SEQ / 32, BATCH), dim3(32, 8)>>>(
        v_x, vt, SEQ, CDIM, (long long)SEQ * CDIM, (long long)CDIM * SEQ);
    colsum_v<<<dim3(CDIM / 256, BATCH), 256>>>(v_x, colsum);

    // 2) MT[c'][c] = sum_d WkT[c'][d] * WqT[c][d]  (= M[c][c'])
    gemm_mma<0><<<dim3(CDIM / BN, KD / BM, 1), 256, GSMEM_BYTES>>>(
        wt + nw, wt, nullptr, mt, nullptr, nullptr, 0.f, KD, CDIM, 0, 0, 0);

    // 3) q'[m][c'] = sum_c qx[m][c] * MT[c'][c]
    gemm_mma<0><<<dim3(KD / BN, MQ / BM, 1), 256, GSMEM_BYTES>>>(
        qx, mt, nullptr, qp, nullptr, nullptr, 0.f, CDIM, KD, 0, 0, 0);

    // 4) E' = exp((q' @ kx^T) * scale) - 1  per batch (bf16)
    gemm_mma<3><<<dim3(SEQ / BN, SEQ / BM, BATCH), 256, GSMEM_BYTES>>>(
        qp, kx, nullptr, e, nullptr, nullptr, 1.0f / (float)KD, KD, SEQ,
        (long long)SEQ * KD, (long long)SEQ * CDIM, (long long)SEQ * SEQ);

    // 5) inv_denom[m] = 1 / (SEQ + rowsum(E'))
    rowsum_exp<<<MQ, 256>>>(e, inv);

    // 6) out = (E' @ Vt^T + colsum) * inv_denom  per batch (fp32)
    gemm_mma<4><<<dim3(CDIM / BN, SEQ / BM, BATCH), 256, GSMEM_BYTES>>>(
        e, vt, out, nullptr, colsum, inv, 0.f, SEQ, CDIM,
        (long long)SEQ * SEQ, (long long)CDIM * SEQ, (long long)SEQ * CDIM);
}

// round 15
// speedup vs baseline: 1.0836x; 1.0254x over previous
#include <cuda_runtime.h>
#include <cuda_bf16.h>
#include <cstdint>

#define BATCH 8
#define SEQ   2048
#define CDIM  768
#define KD    768
#define MQ    (BATCH*SEQ)

typedef __nv_bfloat16 bf16;

// ---------------- scratch (device globals; allocation-free rule) -------------
__device__ bf16  g_qx[(size_t)MQ*CDIM];              // qx bf16
__device__ bf16  g_kx[(size_t)MQ*CDIM];              // kx bf16
__device__ bf16  g_wt[(size_t)2*KD*CDIM];            // WqT, WkT bf16
__device__ bf16  g_mt[(size_t)KD*CDIM];              // MT[c'][c] = M[c][c']
__device__ bf16  g_qp[(size_t)MQ*KD];                // q' = qx @ M
__device__ bf16  g_e [(size_t)BATCH*SEQ*SEQ];        // E' = exp(S*scale)-1
__device__ bf16  g_vt[(size_t)BATCH*CDIM*SEQ];       // V^T bf16
__device__ float g_colsum[(size_t)BATCH*CDIM];       // colsum of V (fp32 exact)
__device__ float g_epart[(size_t)MQ*16];             // per-(row, n-tile) partial Σexp
__device__ float g_inv  [(size_t)MQ];                // 1/(SEQ + rowsum(E'))

// ---------------- helpers ----------------------------------------------------
__device__ __forceinline__ uint32_t smem_u32(const void* p) {
    uint32_t a;
    asm("{ .reg .u64 t; cvta.to.shared.u64 t, %1; cvt.u32.u64 %0, t; }" : "=r"(a) : "l"(p));
    return a;
}
__device__ __forceinline__ void cp16(uint32_t dst, const void* src) {
    asm volatile("cp.async.cg.shared.global [%0], [%1], 16;" :: "r"(dst), "l"(src));
}
__device__ __forceinline__ void cp_commit() {
    asm volatile("cp.async.commit_group;" ::: "memory");
}
template <int N>
__device__ __forceinline__ void cp_wait() {
    asm volatile("cp.async.wait_group %0;" :: "n"(N) : "memory");
}
__device__ __forceinline__ void ldsm4(uint32_t* r, uint32_t addr) {
    asm volatile("ldmatrix.sync.aligned.m8n8.x4.shared.b16 {%0,%1,%2,%3}, [%4];"
                 : "=r"(r[0]), "=r"(r[1]), "=r"(r[2]), "=r"(r[3]) : "r"(addr));
}
__device__ __forceinline__ void mma16816(float* c, const uint32_t* a, const uint32_t* b) {
    asm volatile(
        "mma.sync.aligned.m16n8k16.row.col.f32.bf16.bf16.f32 "
        "{%0,%1,%2,%3}, {%4,%5,%6,%7}, {%8,%9}, {%0,%1,%2,%3};"
        : "+f"(c[0]), "+f"(c[1]), "+f"(c[2]), "+f"(c[3])
        : "r"(a[0]), "r"(a[1]), "r"(a[2]), "r"(a[3]), "r"(b[0]), "r"(b[1]));
}

// ---------------- single-bf16 NT GEMM via mma.sync ---------------------------
// C[m,n] = sum_k A[m,k]*B[n,k]; A,B bf16, K-major, fp32 accum.
// Block 128x128, K-chunk 64, 3-stage cp.async pipeline, 8 warps (64x32 each),
// register-level fragment double-buffering.
// MODE 0: C -> bf16 plain.
// MODE 3: C -> bf16 of (exp(c*scale)-1); per-row partial sums -> Cf[m*16+bx].
// MODE 4: C -> fp32 of (c + colsum[n]) * inv_denom[m].
#define BM 128
#define BN 128
#define BK 64
#define KSTEPS (BK/16)           // 4
#define STAGES 3
#define PITCH_B 144              // bytes per smem row (64 bf16 + 16 pad)
#define MAT_B  (128*PITCH_B)     // 18432 bytes per matrix tile
#define STAGE_B (2*MAT_B)        // 36864
#define GSMEM_BYTES (STAGES*STAGE_B)   // 110592

template <int MODE>
__global__ void __launch_bounds__(256) gemm_mma(
    const bf16* __restrict__ A, const bf16* __restrict__ B,
    float* __restrict__ Cf, bf16* __restrict__ Cb16,
    const float* __restrict__ bias, const float* __restrict__ denom, float scale,
    int K, int N, long long sA, long long sB, long long sC)
{
    extern __shared__ char smem[];
    const uint32_t smem0 = smem_u32(smem);

    const int tid = threadIdx.x;
    const int wid = tid >> 5;
    const int lane = tid & 31;
    const int m0 = blockIdx.y * BM;
    const int n0 = blockIdx.x * BN;
    const int warp_m = (wid & 1) * 64;
    const int warp_n = (wid >> 1) * 32;

    const bf16* pA = A + (size_t)blockIdx.z * sA;
    const bf16* pB = B + (size_t)blockIdx.z * sB;

    float acc[4][4][4];
#pragma unroll
    for (int a = 0; a < 4; a++)
#pragma unroll
        for (int b = 0; b < 4; b++)
#pragma unroll
            for (int c = 0; c < 4; c++) acc[a][b][c] = 0.0f;

    const int nch = K / BK;

    // stage loader: A 128 rows + B 128 rows, 128B each = 8 cp16/thread
    auto load_stage = [&](int buf, int k0) {
        const uint32_t sb = smem0 + (uint32_t)buf * STAGE_B;
#pragma unroll
        for (int p = 0; p < 4; p++) {
            const int task = tid + p * 256;
            const int row = task >> 3;            // 8 segs per row
            const int seg = task & 7;
            const uint32_t off = (uint32_t)(row * PITCH_B + seg * 16);
            const int ge = k0 + seg * 8;
            cp16(sb +         off, pA + (size_t)(m0 + row) * K + ge);
            cp16(sb + MAT_B + off, pB + (size_t)(n0 + row) * K + ge);
        }
    };

#pragma unroll
    for (int s = 0; s < STAGES - 1; s++) {
        if (s < nch) load_stage(s, s * BK);
        cp_commit();
    }

    const uint32_t a_off = (uint32_t)((lane & 15) * PITCH_B + ((lane >> 4) << 3) * 2);
    const uint32_t b_off = (uint32_t)(((((lane >> 4) << 3) + (lane & 7)) * PITCH_B)
                                      + (((lane >> 3) & 1) << 3) * 2);

    uint32_t ar[2][4][4];       // fragment double buffers
    uint32_t br[2][2][4];

    for (int ch = 0; ch < nch; ch++) {
        cp_wait<STAGES - 2>();
        __syncthreads();

        const int nxt = ch + STAGES - 1;
        if (nxt < nch) load_stage(nxt % STAGES, nxt * BK);
        cp_commit();

        const uint32_t sb = smem0 + (uint32_t)(ch % STAGES) * STAGE_B;
        const uint32_t sA_ = sb, sB_ = sb + MAT_B;

        auto load_frags = [&](int ks, int pb) {
            const uint32_t kb = (uint32_t)(ks * 32);
#pragma unroll
            for (int mi = 0; mi < 4; mi++)
                ldsm4(ar[pb][mi], sA_ + (uint32_t)((warp_m + mi * 16) * PITCH_B) + a_off + kb);
#pragma unroll
            for (int nj = 0; nj < 2; nj++)
                ldsm4(br[pb][nj], sB_ + (uint32_t)((warp_n + nj * 16) * PITCH_B) + b_off + kb);
        };

        load_frags(0, 0);
#pragma unroll
        for (int ks = 0; ks < KSTEPS; ks++) {
            const int cur = ks & 1;
            if (ks + 1 < KSTEPS) load_frags(ks + 1, cur ^ 1);
#pragma unroll
            for (int mi = 0; mi < 4; mi++)
#pragma unroll
                for (int ni = 0; ni < 4; ni++)
                    mma16816(acc[mi][ni], ar[cur][mi], &br[cur][ni >> 1][(ni & 1) * 2]);
        }
    }
    cp_wait<0>();

    // -------- epilogue ------------------------------------------------------
    float rsum_lo[4], rsum_hi[4];
#pragma unroll
    for (int i = 0; i < 4; i++) { rsum_lo[i] = 0.f; rsum_hi[i] = 0.f; }

#pragma unroll
    for (int mi = 0; mi < 4; mi++) {
#pragma unroll
        for (int ni = 0; ni < 4; ni++) {
            const int m = m0 + warp_m + mi * 16 + (lane >> 2);
            const int n = n0 + warp_n + ni * 8 + (lane & 3) * 2;
            float c0 = acc[mi][ni][0], c1 = acc[mi][ni][1];
            float c2 = acc[mi][ni][2], c3 = acc[mi][ni][3];
            if (MODE == 0 || MODE == 3) {
                if (MODE == 3) {
                    c0 = __expf(c0 * scale) - 1.0f;
                    c1 = __expf(c1 * scale) - 1.0f;
                    c2 = __expf(c2 * scale) - 1.0f;
                    c3 = __expf(c3 * scale) - 1.0f;
                    rsum_lo[mi] += c0 + c1;
                    rsum_hi[mi] += c2 + c3;
                }
                bf16* Cz = Cb16 + (size_t)blockIdx.z * sC;
                __nv_bfloat162 h0 = __floats2bfloat162_rn(c0, c1);
                __nv_bfloat162 h1 = __floats2bfloat162_rn(c2, c3);
                *(uint32_t*)(Cz + (size_t)m * N + n)       = reinterpret_cast<uint32_t&>(h0);
                *(uint32_t*)(Cz + (size_t)(m + 8) * N + n) = reinterpret_cast<uint32_t&>(h1);
            } else {  // MODE 4
                float* Cb = Cf + (size_t)blockIdx.z * sC;
                float2 bv = *(const float2*)(bias + (size_t)blockIdx.z * CDIM + n);
                float i0 = denom[(size_t)blockIdx.z * SEQ + m];
                float i1 = denom[(size_t)blockIdx.z * SEQ + m + 8];
                *(float2*)(Cb + (size_t)m * N + n) =
                    make_float2((c0 + bv.x) * i0, (c1 + bv.y) * i0);
                *(float2*)(Cb + (size_t)(m + 8) * N + n) =
                    make_float2((c2 + bv.x) * i1, (c3 + bv.y) * i1);
            }
        }
    }

    if (MODE == 3) {
        // per-CTA row partial sums -> Cf[(bz*SEQ + m0 + r)*16 + bx]
        __syncthreads();                       // all warps done with pipeline smem
        float* sums = reinterpret_cast<float*>(smem);   // [128][4]
#pragma unroll
        for (int mi = 0; mi < 4; mi++) {
            float a = rsum_lo[mi], b = rsum_hi[mi];
            a += __shfl_xor_sync(0xFFFFFFFFu, a, 1);
            a += __shfl_xor_sync(0xFFFFFFFFu, a, 2);
            b += __shfl_xor_sync(0xFFFFFFFFu, b, 1);
            b += __shfl_xor_sync(0xFFFFFFFFu, b, 2);
            if ((lane & 3) == 0) {
                const int r = warp_m + mi * 16 + (lane >> 2);
                sums[r * 4 + (wid >> 1)]       = a;
                sums[(r + 8) * 4 + (wid >> 1)] = b;
            }
        }
        __syncthreads();
        if (tid < 128) {
            float s = sums[tid * 4] + sums[tid * 4 + 1]
                    + sums[tid * 4 + 2] + sums[tid * 4 + 3];
            Cf[((size_t)blockIdx.z * SEQ + m0 + tid) * 16 + blockIdx.x] = s;
        }
    }
}

// ---------------- elementwise fp32 -> bf16 -----------------------------------
__global__ void __launch_bounds__(256) convert_hi(
    const float* __restrict__ x, bf16* __restrict__ h, size_t n)
{
    size_t i = ((size_t)blockIdx.x * 256 + threadIdx.x) * 8;
    if (i >= n) return;
    float4 a = *(const float4*)(x + i);
    float4 b = *(const float4*)(x + i + 4);
    __nv_bfloat162 h0 = __floats2bfloat162_rn(a.x, a.y);
    __nv_bfloat162 h1 = __floats2bfloat162_rn(a.z, a.w);
    __nv_bfloat162 h2 = __floats2bfloat162_rn(b.x, b.y);
    __nv_bfloat162 h3 = __floats2bfloat162_rn(b.z, b.w);
    *(uint4*)(h + i) = make_uint4(
        reinterpret_cast<uint32_t&>(h0), reinterpret_cast<uint32_t&>(h1),
        reinterpret_cast<uint32_t&>(h2), reinterpret_cast<uint32_t&>(h3));
}

// ---------------- generic transpose: [R,C] fp32 -> [C,R] bf16 ----------------
__global__ void __launch_bounds__(256) transpose_convert(
    const float* __restrict__ in, bf16* __restrict__ out,
    int R, int C, long long sIn, long long sOut)
{
    __shared__ float t[32][33];
    const float* ib = in + (size_t)blockIdx.z * sIn;
    bf16* ob = out + (size_t)blockIdx.z * sOut;
    const int c0 = blockIdx.x * 32, r0 = blockIdx.y * 32;
    for (int r = threadIdx.y; r < 32; r += 8)
        t[r][threadIdx.x] = ib[(size_t)(r0 + r) * C + c0 + threadIdx.x];
    __syncthreads();
    for (int r = threadIdx.y; r < 32; r += 8)
        ob[(size_t)(c0 + r) * R + r0 + threadIdx.x] = __float2bfloat16(t[threadIdx.x][r]);
}

// ---------------- column sum of V: colsum[b][c] = sum_n v[b][n][c] ----------
__global__ void __launch_bounds__(256) colsum_v(
    const float* __restrict__ v, float* __restrict__ cs)
{
    const int b = blockIdx.y;
    const int c = blockIdx.x * 256 + threadIdx.x;
    const float* vb = v + (size_t)b * SEQ * CDIM + c;
    float s0 = 0.f, s1 = 0.f, s2 = 0.f, s3 = 0.f;
#pragma unroll 4
    for (int i = 0; i < SEQ; i += 4) {
        s0 += vb[(size_t)(i + 0) * CDIM];
        s1 += vb[(size_t)(i + 1) * CDIM];
        s2 += vb[(size_t)(i + 2) * CDIM];
        s3 += vb[(size_t)(i + 3) * CDIM];
    }
    cs[(size_t)b * CDIM + c] = s0 + s1 + s2 + s3;
}

// ---------------- final: inv[m] = 1/(SEQ + sum of 16 partials) --------------
__global__ void __launch_bounds__(256) rowsum_final(
    const float* __restrict__ part, float* __restrict__ inv)
{
    const int m = blockIdx.x * 256 + threadIdx.x;
    const float* p = part + (size_t)m * 16;
    float s = 0.f;
#pragma unroll
    for (int j = 0; j < 16; j++) s += p[j];
    inv[m] = 1.0f / ((float)SEQ + s);
}

// ---------------- launch -----------------------------------------------------
extern "C" void kernel_launch(void* const* d_in, const int* in_sizes, int n_in,
                              void* d_out, int out_size)
{
    const float* q_x = (const float*)d_in[0];
    const float* k_x = (const float*)d_in[1];
    const float* v_x = (const float*)d_in[2];
    const float* Wq  = (const float*)d_in[3];
    const float* Wk  = (const float*)d_in[4];
    float* out = (float*)d_out;

    bf16 *qx, *kx, *wt, *mt, *qp, *e, *vt;
    float *colsum, *epart, *inv;
    cudaGetSymbolAddress((void**)&qx, g_qx);
    cudaGetSymbolAddress((void**)&kx, g_kx);
    cudaGetSymbolAddress((void**)&wt, g_wt);
    cudaGetSymbolAddress((void**)&mt, g_mt);
    cudaGetSymbolAddress((void**)&qp, g_qp);
    cudaGetSymbolAddress((void**)&e,  g_e);
    cudaGetSymbolAddress((void**)&vt, g_vt);
    cudaGetSymbolAddress((void**)&colsum, g_colsum);
    cudaGetSymbolAddress((void**)&epart, g_epart);
    cudaGetSymbolAddress((void**)&inv, g_inv);

    cudaFuncSetAttribute(gemm_mma<0>, cudaFuncAttributeMaxDynamicSharedMemorySize, GSMEM_BYTES);
    cudaFuncSetAttribute(gemm_mma<3>, cudaFuncAttributeMaxDynamicSharedMemorySize, GSMEM_BYTES);
    cudaFuncSetAttribute(gemm_mma<4>, cudaFuncAttributeMaxDynamicSharedMemorySize, GSMEM_BYTES);

    const size_t nx = (size_t)MQ * CDIM;
    const size_t nw = (size_t)KD * CDIM;

    // 1) converts / transposes / V colsum
    convert_hi<<<(unsigned)(nx / 8 / 256), 256>>>(q_x, qx, nx);
    convert_hi<<<(unsigned)(nx / 8 / 256), 256>>>(k_x, kx, nx);
    transpose_convert<<<dim3(CDIM / 32, KD / 32, 1), dim3(32, 8)>>>(
        Wq, wt, KD, CDIM, 0, 0);                         // WqT [c][d]
    transpose_convert<<<dim3(CDIM / 32, KD / 32, 1), dim3(32, 8)>>>(
        Wk, wt + nw, KD, CDIM, 0, 0);                    // WkT [c'][d]
    transpose_convert<<<dim3(CDIM / 32, SEQ / 32, BATCH), dim3(32, 8)>>>(
        v_x, vt, SEQ, CDIM, (long long)SEQ * CDIM, (long long)CDIM * SEQ);
    colsum_v<<<dim3(CDIM / 256, BATCH), 256>>>(v_x, colsum);

    // 2) MT[c'][c] = sum_d WkT[c'][d] * WqT[c][d]  (= M[c][c'])
    gemm_mma<0><<<dim3(CDIM / BN, KD / BM, 1), 256, GSMEM_BYTES>>>(
        wt + nw, wt, nullptr, mt, nullptr, nullptr, 0.f, KD, CDIM, 0, 0, 0);

    // 3) q'[m][c'] = sum_c qx[m][c] * MT[c'][c]
    gemm_mma<0><<<dim3(KD / BN, MQ / BM, 1), 256, GSMEM_BYTES>>>(
        qx, mt, nullptr, qp, nullptr, nullptr, 0.f, CDIM, KD, 0, 0, 0);

    // 4) E' = exp((q' @ kx^T) * scale) - 1 (bf16) + per-CTA row partials
    gemm_mma<3><<<dim3(SEQ / BN, SEQ / BM, BATCH), 256, GSMEM_BYTES>>>(
        qp, kx, epart, e, nullptr, nullptr, 1.0f / (float)KD, KD, SEQ,
        (long long)SEQ * KD, (long long)SEQ * CDIM, (long long)SEQ * SEQ);

    // 5) inv_denom[m] = 1 / (SEQ + sum of partials)
    rowsum_final<<<MQ / 256, 256>>>(epart, inv);

    // 6) out = (E' @ Vt^T + colsum) * inv_denom  per batch (fp32)
    gemm_mma<4><<<dim3(CDIM / BN, SEQ / BM, BATCH), 256, GSMEM_BYTES>>>(
        e, vt, out, nullptr, colsum, inv, 0.f, SEQ, CDIM,
        (long long)SEQ * SEQ, (long long)CDIM * SEQ, (long long)SEQ * CDIM);
}

// round 16
// speedup vs baseline: 1.0937x; 1.0093x over previous
#include <cuda_runtime.h>
#include <cuda_bf16.h>
#include <cstdint>

#define BATCH 8
#define SEQ   2048
#define CDIM  768
#define KD    768
#define MQ    (BATCH*SEQ)

typedef __nv_bfloat16 bf16;

// ---------------- scratch (device globals; allocation-free rule) -------------
__device__ bf16  g_qx[(size_t)MQ*CDIM];              // qx bf16
__device__ bf16  g_kx[(size_t)MQ*CDIM];              // kx bf16
__device__ bf16  g_wt[(size_t)2*KD*CDIM];            // WqT, WkT bf16
__device__ bf16  g_mt[(size_t)KD*CDIM];              // MT[c'][c] = M[c][c']
__device__ bf16  g_qp[(size_t)MQ*KD];                // q' = qx @ M
__device__ bf16  g_e [(size_t)BATCH*SEQ*SEQ];        // E' = exp(S*scale)-1
__device__ bf16  g_vt[(size_t)BATCH*CDIM*SEQ];       // V^T bf16
__device__ float g_colsum[(size_t)BATCH*CDIM];       // colsum of V (fp32 exact)
__device__ float g_epart[(size_t)MQ*16];             // per-(row, n-tile) partial Σexp

// ---------------- helpers ----------------------------------------------------
__device__ __forceinline__ uint32_t smem_u32(const void* p) {
    uint32_t a;
    asm("{ .reg .u64 t; cvta.to.shared.u64 t, %1; cvt.u32.u64 %0, t; }" : "=r"(a) : "l"(p));
    return a;
}
__device__ __forceinline__ void cp16(uint32_t dst, const void* src) {
    asm volatile("cp.async.cg.shared.global [%0], [%1], 16;" :: "r"(dst), "l"(src));
}
__device__ __forceinline__ void cp_commit() {
    asm volatile("cp.async.commit_group;" ::: "memory");
}
template <int N>
__device__ __forceinline__ void cp_wait() {
    asm volatile("cp.async.wait_group %0;" :: "n"(N) : "memory");
}
__device__ __forceinline__ void ldsm4(uint32_t* r, uint32_t addr) {
    asm volatile("ldmatrix.sync.aligned.m8n8.x4.shared.b16 {%0,%1,%2,%3}, [%4];"
                 : "=r"(r[0]), "=r"(r[1]), "=r"(r[2]), "=r"(r[3]) : "r"(addr));
}
__device__ __forceinline__ void mma16816(float* c, const uint32_t* a, const uint32_t* b) {
    asm volatile(
        "mma.sync.aligned.m16n8k16.row.col.f32.bf16.bf16.f32 "
        "{%0,%1,%2,%3}, {%4,%5,%6,%7}, {%8,%9}, {%0,%1,%2,%3};"
        : "+f"(c[0]), "+f"(c[1]), "+f"(c[2]), "+f"(c[3])
        : "r"(a[0]), "r"(a[1]), "r"(a[2]), "r"(a[3]), "r"(b[0]), "r"(b[1]));
}

// ---------------- single-bf16 NT GEMM via mma.sync ---------------------------
// C[m,n] = sum_k A[m,k]*B[n,k]; A,B bf16, K-major, fp32 accum.
// Block 128x128, K-chunk 64, 3-stage cp.async pipeline, 8 warps (64x32 each),
// register-level fragment double-buffering.
// MODE 0: C -> bf16 plain.
// MODE 3: C -> bf16 of (exp(c*scale)-1); per-row partial sums -> Cf[m*16+bx].
// MODE 4: C -> fp32 of (c + colsum[n]) * inv[m], inv computed in-kernel from
//         the 16 per-row partials (denom = epart base pointer).
#define BM 128
#define BN 128
#define BK 64
#define KSTEPS (BK/16)           // 4
#define STAGES 3
#define PITCH_B 144              // bytes per smem row (64 bf16 + 16 pad)
#define MAT_B  (128*PITCH_B)     // 18432 bytes per matrix tile
#define STAGE_B (2*MAT_B)        // 36864
#define GSMEM_BYTES (STAGES*STAGE_B)   // 110592

template <int MODE>
__global__ void __launch_bounds__(256) gemm_mma(
    const bf16* __restrict__ A, const bf16* __restrict__ B,
    float* __restrict__ Cf, bf16* __restrict__ Cb16,
    const float* __restrict__ bias, const float* __restrict__ denom, float scale,
    int K, int N, long long sA, long long sB, long long sC)
{
    extern __shared__ char smem[];
    const uint32_t smem0 = smem_u32(smem);
    __shared__ float sinv[128];            // MODE 4 only: per-row inv_denom

    const int tid = threadIdx.x;
    const int wid = tid >> 5;
    const int lane = tid & 31;
    const int m0 = blockIdx.y * BM;
    const int n0 = blockIdx.x * BN;
    const int warp_m = (wid & 1) * 64;
    const int warp_n = (wid >> 1) * 32;

    const bf16* pA = A + (size_t)blockIdx.z * sA;
    const bf16* pB = B + (size_t)blockIdx.z * sB;

    if (MODE == 4 && tid < 128) {
        // inv[m] = 1/(SEQ + sum_j part[m][j]); same j-order as old rowsum_final
        const float* p = denom + ((size_t)blockIdx.z * SEQ + m0 + tid) * 16;
        float s = 0.f;
#pragma unroll
        for (int j = 0; j < 16; j++) s += p[j];
        sinv[tid] = 1.0f / ((float)SEQ + s);
    }

    float acc[4][4][4];
#pragma unroll
    for (int a = 0; a < 4; a++)
#pragma unroll
        for (int b = 0; b < 4; b++)
#pragma unroll
            for (int c = 0; c < 4; c++) acc[a][b][c] = 0.0f;

    const int nch = K / BK;

    // stage loader: A 128 rows + B 128 rows, 128B each = 8 cp16/thread
    auto load_stage = [&](int buf, int k0) {
        const uint32_t sb = smem0 + (uint32_t)buf * STAGE_B;
#pragma unroll
        for (int p = 0; p < 4; p++) {
            const int task = tid + p * 256;
            const int row = task >> 3;            // 8 segs per row
            const int seg = task & 7;
            const uint32_t off = (uint32_t)(row * PITCH_B + seg * 16);
            const int ge = k0 + seg * 8;
            cp16(sb +         off, pA + (size_t)(m0 + row) * K + ge);
            cp16(sb + MAT_B + off, pB + (size_t)(n0 + row) * K + ge);
        }
    };

#pragma unroll
    for (int s = 0; s < STAGES - 1; s++) {
        if (s < nch) load_stage(s, s * BK);
        cp_commit();
    }

    const uint32_t a_off = (uint32_t)((lane & 15) * PITCH_B + ((lane >> 4) << 3) * 2);
    const uint32_t b_off = (uint32_t)(((((lane >> 4) << 3) + (lane & 7)) * PITCH_B)
                                      + (((lane >> 3) & 1) << 3) * 2);

    uint32_t ar[2][4][4];       // fragment double buffers
    uint32_t br[2][2][4];

    for (int ch = 0; ch < nch; ch++) {
        cp_wait<STAGES - 2>();
        __syncthreads();

        const int nxt = ch + STAGES - 1;
        if (nxt < nch) load_stage(nxt % STAGES, nxt * BK);
        cp_commit();

        const uint32_t sb = smem0 + (uint32_t)(ch % STAGES) * STAGE_B;
        const uint32_t sA_ = sb, sB_ = sb + MAT_B;

        auto load_frags = [&](int ks, int pb) {
            const uint32_t kb = (uint32_t)(ks * 32);
#pragma unroll
            for (int mi = 0; mi < 4; mi++)
                ldsm4(ar[pb][mi], sA_ + (uint32_t)((warp_m + mi * 16) * PITCH_B) + a_off + kb);
#pragma unroll
            for (int nj = 0; nj < 2; nj++)
                ldsm4(br[pb][nj], sB_ + (uint32_t)((warp_n + nj * 16) * PITCH_B) + b_off + kb);
        };

        load_frags(0, 0);
#pragma unroll
        for (int ks = 0; ks < KSTEPS; ks++) {
            const int cur = ks & 1;
            if (ks + 1 < KSTEPS) load_frags(ks + 1, cur ^ 1);
#pragma unroll
            for (int mi = 0; mi < 4; mi++)
#pragma unroll
                for (int ni = 0; ni < 4; ni++)
                    mma16816(acc[mi][ni], ar[cur][mi], &br[cur][ni >> 1][(ni & 1) * 2]);
        }
    }
    cp_wait<0>();

    // -------- epilogue ------------------------------------------------------
    float rsum_lo[4], rsum_hi[4];
#pragma unroll
    for (int i = 0; i < 4; i++) { rsum_lo[i] = 0.f; rsum_hi[i] = 0.f; }

#pragma unroll
    for (int mi = 0; mi < 4; mi++) {
#pragma unroll
        for (int ni = 0; ni < 4; ni++) {
            const int lr = warp_m + mi * 16 + (lane >> 2);       // local row
            const int m = m0 + lr;
            const int n = n0 + warp_n + ni * 8 + (lane & 3) * 2;
            float c0 = acc[mi][ni][0], c1 = acc[mi][ni][1];
            float c2 = acc[mi][ni][2], c3 = acc[mi][ni][3];
            if (MODE == 0 || MODE == 3) {
                if (MODE == 3) {
                    c0 = __expf(c0 * scale) - 1.0f;
                    c1 = __expf(c1 * scale) - 1.0f;
                    c2 = __expf(c2 * scale) - 1.0f;
                    c3 = __expf(c3 * scale) - 1.0f;
                    rsum_lo[mi] += c0 + c1;
                    rsum_hi[mi] += c2 + c3;
                }
                bf16* Cz = Cb16 + (size_t)blockIdx.z * sC;
                __nv_bfloat162 h0 = __floats2bfloat162_rn(c0, c1);
                __nv_bfloat162 h1 = __floats2bfloat162_rn(c2, c3);
                *(uint32_t*)(Cz + (size_t)m * N + n)       = reinterpret_cast<uint32_t&>(h0);
                *(uint32_t*)(Cz + (size_t)(m + 8) * N + n) = reinterpret_cast<uint32_t&>(h1);
            } else {  // MODE 4
                float* Cb = Cf + (size_t)blockIdx.z * sC;
                float2 bv = *(const float2*)(bias + (size_t)blockIdx.z * CDIM + n);
                float i0 = sinv[lr];
                float i1 = sinv[lr + 8];
                *(float2*)(Cb + (size_t)m * N + n) =
                    make_float2((c0 + bv.x) * i0, (c1 + bv.y) * i0);
                *(float2*)(Cb + (size_t)(m + 8) * N + n) =
                    make_float2((c2 + bv.x) * i1, (c3 + bv.y) * i1);
            }
        }
    }

    if (MODE == 3) {
        // per-CTA row partial sums -> Cf[(bz*SEQ + m0 + r)*16 + bx]
        __syncthreads();                       // all warps done with pipeline smem
        float* sums = reinterpret_cast<float*>(smem);   // [128][4]
#pragma unroll
        for (int mi = 0; mi < 4; mi++) {
            float a = rsum_lo[mi], b = rsum_hi[mi];
            a += __shfl_xor_sync(0xFFFFFFFFu, a, 1);
            a += __shfl_xor_sync(0xFFFFFFFFu, a, 2);
            b += __shfl_xor_sync(0xFFFFFFFFu, b, 1);
            b += __shfl_xor_sync(0xFFFFFFFFu, b, 2);
            if ((lane & 3) == 0) {
                const int r = warp_m + mi * 16 + (lane >> 2);
                sums[r * 4 + (wid >> 1)]       = a;
                sums[(r + 8) * 4 + (wid >> 1)] = b;
            }
        }
        __syncthreads();
        if (tid < 128) {
            float s = sums[tid * 4] + sums[tid * 4 + 1]
                    + sums[tid * 4 + 2] + sums[tid * 4 + 3];
            Cf[((size_t)blockIdx.z * SEQ + m0 + tid) * 16 + blockIdx.x] = s;
        }
    }
}

// ---------------- elementwise fp32 -> bf16 (2 sources in one launch) ---------
__global__ void __launch_bounds__(256) convert_hi2(
    const float* __restrict__ x0, bf16* __restrict__ h0p,
    const float* __restrict__ x1, bf16* __restrict__ h1p, size_t n)
{
    const float* x = blockIdx.y ? x1 : x0;
    bf16* h = blockIdx.y ? h1p : h0p;
    size_t i = ((size_t)blockIdx.x * 256 + threadIdx.x) * 8;
    if (i >= n) return;
    float4 a = *(const float4*)(x + i);
    float4 b = *(const float4*)(x + i + 4);
    __nv_bfloat162 h0 = __floats2bfloat162_rn(a.x, a.y);
    __nv_bfloat162 h1 = __floats2bfloat162_rn(a.z, a.w);
    __nv_bfloat162 h2 = __floats2bfloat162_rn(b.x, b.y);
    __nv_bfloat162 h3 = __floats2bfloat162_rn(b.z, b.w);
    *(uint4*)(h + i) = make_uint4(
        reinterpret_cast<uint32_t&>(h0), reinterpret_cast<uint32_t&>(h1),
        reinterpret_cast<uint32_t&>(h2), reinterpret_cast<uint32_t&>(h3));
}

// ---------------- generic transpose: [R,C] fp32 -> [C,R] bf16 ----------------
// grid.z indexes independent (src,dst) slabs with strides sIn/sOut.
__global__ void __launch_bounds__(256) transpose_convert(
    const float* __restrict__ in, bf16* __restrict__ out,
    int R, int C, long long sIn, long long sOut)
{
    __shared__ float t[32][33];
    const float* ib = in + (size_t)blockIdx.z * sIn;
    bf16* ob = out + (size_t)blockIdx.z * sOut;
    const int c0 = blockIdx.x * 32, r0 = blockIdx.y * 32;
    for (int r = threadIdx.y; r < 32; r += 8)
        t[r][threadIdx.x] = ib[(size_t)(r0 + r) * C + c0 + threadIdx.x];
    __syncthreads();
    for (int r = threadIdx.y; r < 32; r += 8)
        ob[(size_t)(c0 + r) * R + r0 + threadIdx.x] = __float2bfloat16(t[threadIdx.x][r]);
}

// Wq/Wk transpose pair in one launch: z=0 -> Wq, z=1 -> Wk
__global__ void __launch_bounds__(256) transpose_convert_w(
    const float* __restrict__ wq, const float* __restrict__ wk,
    bf16* __restrict__ out)
{
    __shared__ float t[32][33];
    const float* ib = blockIdx.z ? wk : wq;
    bf16* ob = out + (size_t)blockIdx.z * KD * CDIM;
    const int c0 = blockIdx.x * 32, r0 = blockIdx.y * 32;
    for (int r = threadIdx.y; r < 32; r += 8)
        t[r][threadIdx.x] = ib[(size_t)(r0 + r) * CDIM + c0 + threadIdx.x];
    __syncthreads();
    for (int r = threadIdx.y; r < 32; r += 8)
        ob[(size_t)(c0 + r) * KD + r0 + threadIdx.x] = __float2bfloat16(t[threadIdx.x][r]);
}

// ---------------- column sum of V: colsum[b][c] = sum_n v[b][n][c] ----------
__global__ void __launch_bounds__(256) colsum_v(
    const float* __restrict__ v, float* __restrict__ cs)
{
    const int b = blockIdx.y;
    const int c = blockIdx.x * 256 + threadIdx.x;
    const float* vb = v + (size_t)b * SEQ * CDIM + c;
    float s0 = 0.f, s1 = 0.f, s2 = 0.f, s3 = 0.f;
#pragma unroll 4
    for (int i = 0; i < SEQ; i += 4) {
        s0 += vb[(size_t)(i + 0) * CDIM];
        s1 += vb[(size_t)(i + 1) * CDIM];
        s2 += vb[(size_t)(i + 2) * CDIM];
        s3 += vb[(size_t)(i + 3) * CDIM];
    }
    cs[(size_t)b * CDIM + c] = s0 + s1 + s2 + s3;
}

// ---------------- launch -----------------------------------------------------
extern "C" void kernel_launch(void* const* d_in, const int* in_sizes, int n_in,
                              void* d_out, int out_size)
{
    const float* q_x = (const float*)d_in[0];
    const float* k_x = (const float*)d_in[1];
    const float* v_x = (const float*)d_in[2];
    const float* Wq  = (const float*)d_in[3];
    const float* Wk  = (const float*)d_in[4];
    float* out = (float*)d_out;

    bf16 *qx, *kx, *wt, *mt, *qp, *e, *vt;
    float *colsum, *epart;
    cudaGetSymbolAddress((void**)&qx, g_qx);
    cudaGetSymbolAddress((void**)&kx, g_kx);
    cudaGetSymbolAddress((void**)&wt, g_wt);
    cudaGetSymbolAddress((void**)&mt, g_mt);
    cudaGetSymbolAddress((void**)&qp, g_qp);
    cudaGetSymbolAddress((void**)&e,  g_e);
    cudaGetSymbolAddress((void**)&vt, g_vt);
    cudaGetSymbolAddress((void**)&colsum, g_colsum);
    cudaGetSymbolAddress((void**)&epart, g_epart);

    cudaFuncSetAttribute(gemm_mma<0>, cudaFuncAttributeMaxDynamicSharedMemorySize, GSMEM_BYTES);
    cudaFuncSetAttribute(gemm_mma<3>, cudaFuncAttributeMaxDynamicSharedMemorySize, GSMEM_BYTES);
    cudaFuncSetAttribute(gemm_mma<4>, cudaFuncAttributeMaxDynamicSharedMemorySize, GSMEM_BYTES);

    const size_t nx = (size_t)MQ * CDIM;
    const size_t nw = (size_t)KD * CDIM;

    // 1) converts / transposes / V colsum (merged: 4 launches)
    convert_hi2<<<dim3((unsigned)(nx / 8 / 256), 2), 256>>>(q_x, qx, k_x, kx, nx);
    transpose_convert_w<<<dim3(CDIM / 32, KD / 32, 2), dim3(32, 8)>>>(Wq, Wk, wt);
    transpose_convert<<<dim3(CDIM / 32, SEQ / 32, BATCH), dim3(32, 8)>>>(
        v_x, vt, SEQ, CDIM, (long long)SEQ * CDIM, (long long)CDIM * SEQ);
    colsum_v<<<dim3(CDIM / 256, BATCH), 256>>>(v_x, colsum);

    // 2) MT[c'][c] = sum_d WkT[c'][d] * WqT[c][d]  (= M[c][c'])
    gemm_mma<0><<<dim3(CDIM / BN, KD / BM, 1), 256, GSMEM_BYTES>>>(
        wt + nw, wt, nullptr, mt, nullptr, nullptr, 0.f, KD, CDIM, 0, 0, 0);

    // 3) q'[m][c'] = sum_c qx[m][c] * MT[c'][c]
    gemm_mma<0><<<dim3(KD / BN, MQ / BM, 1), 256, GSMEM_BYTES>>>(
        qx, mt, nullptr, qp, nullptr, nullptr, 0.f, CDIM, KD, 0, 0, 0);

    // 4) E' = exp((q' @ kx^T) * scale) - 1 (bf16) + per-CTA row partials
    gemm_mma<3><<<dim3(SEQ / BN, SEQ / BM, BATCH), 256, GSMEM_BYTES>>>(
        qp, kx, epart, e, nullptr, nullptr, 1.0f / (float)KD, KD, SEQ,
        (long long)SEQ * KD, (long long)SEQ * CDIM, (long long)SEQ * SEQ);

    // 5) out = (E' @ Vt^T + colsum) * inv  per batch (fp32); inv from partials
    gemm_mma<4><<<dim3(CDIM / BN, SEQ / BM, BATCH), 256, GSMEM_BYTES>>>(
        e, vt, out, nullptr, colsum, epart, 0.f, SEQ, CDIM,
        (long long)SEQ * SEQ, (long long)CDIM * SEQ, (long long)SEQ * CDIM);
}